// round 1
// baseline (speedup 1.0000x reference)
#include <cuda_runtime.h>

// RNNModel: B=262144, F=5, T=4, H=128, L=5 tanh RNN + scalar head.
// Strategy: one CTA per 64-row batch tile; all activations Y[4][64][128] in SMEM,
// weights staged (transposed) per phase into SMEM; fp32 register-tiled GEMMs.

#define NB    64          // batch rows per CTA
#define HDIM  128
#define TSEQ  4
#define SY    132         // padded row stride for Y (floats)
#define SW    132         // padded row stride for Wt (floats)
#define NT    256         // threads per CTA
#define NLAYER 5

// SMEM layout (float offsets)
#define OFF_Y    0
#define OFF_W    (TSEQ*NB*SY)            // 33792
#define OFF_XS   (OFF_W + HDIM*SW)       // + 16896 = 50688
#define OFF_B2   (OFF_XS + NB*20)        // + 1280  = 51968
#define OFF_WFC  (OFF_B2 + HDIM)         // + 128   = 52096
#define SMEM_FLOATS (OFF_WFC + HDIM)     // 52224
#define SMEM_BYTES  (SMEM_FLOATS * 4)    // 208896 bytes

// Accurate-enough tanh (~1e-6 rel err): 2 MUFU (ex2, rcp) + few ALU ops.
// Deliberately NOT tanh.approx.f32 (abs err ~6e-4 would compound over 20 steps).
__device__ __forceinline__ float fast_tanh(float x){
    float ax = fabsf(x);
    float e  = __expf(-2.0f * ax);
    float r  = __fdividef(1.0f - e, 1.0f + e);
    return copysignf(r, x);
}

// Load a 128x128 weight matrix g[j][k] (row-major) into SMEM transposed:
// w[k*SW + j]. GMEM reads coalesced (lane -> k); STS.128 along j (4-way conflict,
// minimum possible for a column store; ~4% of runtime total).
__device__ __forceinline__ void load_wt(const float* __restrict__ g,
                                        float* __restrict__ w, int tid){
    int lane = tid & 31, wp = tid >> 5;
    #pragma unroll 4
    for (int it = wp; it < 128; it += 8){      // 32 j-groups x 4 k-groups
        int jg = it >> 2, kg = it & 3;
        int j0 = jg * 4;
        int k  = kg * 32 + lane;
        float v0 = g[(j0+0)*HDIM + k];
        float v1 = g[(j0+1)*HDIM + k];
        float v2 = g[(j0+2)*HDIM + k];
        float v3 = g[(j0+3)*HDIM + k];
        *(float4*)(w + k*SW + j0) = make_float4(v0, v1, v2, v3);
    }
}

// C[b0..b0+3][j0..j0+7] += A[b][k] * Wt[k][j]  over k=0..127.
// A rows: float4 over k (warp-broadcast across tx). W: float4 over j (conflict-free).
__device__ __forceinline__ void gemm_tile(const float* __restrict__ A,
                                          const float* __restrict__ W,
                                          float acc[4][8], int b0, int j0){
    const float* a0 = A + (b0+0)*SY;
    const float* a1 = A + (b0+1)*SY;
    const float* a2 = A + (b0+2)*SY;
    const float* a3 = A + (b0+3)*SY;
    const float* wp = W + j0;
    #pragma unroll 2
    for (int k = 0; k < HDIM; k += 4){
        float4 va[4];
        va[0] = *(const float4*)(a0 + k);
        va[1] = *(const float4*)(a1 + k);
        va[2] = *(const float4*)(a2 + k);
        va[3] = *(const float4*)(a3 + k);
        #pragma unroll
        for (int kk = 0; kk < 4; kk++){
            float4 w0 = *(const float4*)(wp + (k+kk)*SW);
            float4 w1 = *(const float4*)(wp + (k+kk)*SW + 4);
            #pragma unroll
            for (int i = 0; i < 4; i++){
                float av = ((const float*)(va + i))[kk];
                acc[i][0] = fmaf(av, w0.x, acc[i][0]);
                acc[i][1] = fmaf(av, w0.y, acc[i][1]);
                acc[i][2] = fmaf(av, w0.z, acc[i][2]);
                acc[i][3] = fmaf(av, w0.w, acc[i][3]);
                acc[i][4] = fmaf(av, w1.x, acc[i][4]);
                acc[i][5] = fmaf(av, w1.y, acc[i][5]);
                acc[i][6] = fmaf(av, w1.z, acc[i][6]);
                acc[i][7] = fmaf(av, w1.w, acc[i][7]);
            }
        }
    }
}

__device__ __forceinline__ void store_tile(float* __restrict__ dst,
                                           const float acc[4][8], int b0, int j0){
    #pragma unroll
    for (int i = 0; i < 4; i++){
        *(float4*)(dst + (b0+i)*SY + j0)     = make_float4(acc[i][0],acc[i][1],acc[i][2],acc[i][3]);
        *(float4*)(dst + (b0+i)*SY + j0 + 4) = make_float4(acc[i][4],acc[i][5],acc[i][6],acc[i][7]);
    }
}

// Wts holds W_hh transposed. t=0: h = tanh(xin). t>=1: Y[t] = tanh(Y[t] + Y[t-1] @ Whh^T).
__device__ __forceinline__ void recurrent_phase(float* __restrict__ Yf,
                                                const float* __restrict__ Wts,
                                                int tid, int b0, int j0){
    for (int idx = tid; idx < NB*HDIM; idx += NT){
        int bb = idx >> 7, j = idx & (HDIM-1);
        float* p = Yf + bb*SY + j;
        *p = fast_tanh(*p);
    }
    __syncthreads();
    for (int t = 1; t < TSEQ; t++){
        float acc[4][8];
        #pragma unroll
        for (int i = 0; i < 4; i++){
            float4 p0 = *(const float4*)(Yf + (t*NB + b0 + i)*SY + j0);
            float4 p1 = *(const float4*)(Yf + (t*NB + b0 + i)*SY + j0 + 4);
            acc[i][0]=p0.x; acc[i][1]=p0.y; acc[i][2]=p0.z; acc[i][3]=p0.w;
            acc[i][4]=p1.x; acc[i][5]=p1.y; acc[i][6]=p1.z; acc[i][7]=p1.w;
        }
        gemm_tile(Yf + (t-1)*NB*SY, Wts, acc, b0, j0);
        #pragma unroll
        for (int i = 0; i < 4; i++)
            #pragma unroll
            for (int jj = 0; jj < 8; jj++) acc[i][jj] = fast_tanh(acc[i][jj]);
        __syncthreads();                    // all reads of Y[t-1] & Y[t] done
        store_tile(Yf + t*NB*SY, acc, b0, j0);
        __syncthreads();
    }
}

// Wts holds W_ih transposed. In-place: Y[t] = bias + Y[t] @ Wih^T.
// Safe: each output tile is fully in registers before the barrier + write-back.
__device__ __forceinline__ void input_phase(float* __restrict__ Yf,
                                            const float* __restrict__ Wts,
                                            const float* __restrict__ b2,
                                            int b0, int j0){
    float4 bb0 = *(const float4*)(b2 + j0);
    float4 bb1 = *(const float4*)(b2 + j0 + 4);
    for (int t = 0; t < TSEQ; t++){
        float acc[4][8];
        #pragma unroll
        for (int i = 0; i < 4; i++){
            acc[i][0]=bb0.x; acc[i][1]=bb0.y; acc[i][2]=bb0.z; acc[i][3]=bb0.w;
            acc[i][4]=bb1.x; acc[i][5]=bb1.y; acc[i][6]=bb1.z; acc[i][7]=bb1.w;
        }
        gemm_tile(Yf + t*NB*SY, Wts, acc, b0, j0);
        __syncthreads();
        store_tile(Yf + t*NB*SY, acc, b0, j0);
        __syncthreads();
    }
}

__global__ void __launch_bounds__(NT, 1)
rnn_kernel(const float* __restrict__ x,
           const float* __restrict__ Wih0, const float* __restrict__ Whh0,
           const float* __restrict__ bih0, const float* __restrict__ bhh0,
           const float* __restrict__ WihS, const float* __restrict__ WhhS,
           const float* __restrict__ bihS, const float* __restrict__ bhhS,
           const float* __restrict__ Wfc,  const float* __restrict__ bfc,
           float* __restrict__ out, int Btot)
{
    extern __shared__ float sm[];
    float* Yf  = sm + OFF_Y;
    float* Wts = sm + OFF_W;
    float* xs  = sm + OFF_XS;
    float* b2  = sm + OFF_B2;
    float* wfc = sm + OFF_WFC;

    const int tid = threadIdx.x;
    const int tx = tid & 15, ty = tid >> 4;
    const int b0 = ty * 4, j0 = tx * 8;
    const long long baseb = (long long)blockIdx.x * NB;

    // Stage x tile (b,f,t layout: x[b*20 + f*4 + t]); contiguous & coalesced.
    for (int i = tid; i < NB*20; i += NT){
        long long g = baseb*20 + i;
        xs[i] = (g < (long long)Btot*20) ? x[g] : 0.0f;
    }
    // Layer-0 input weights (128x5) temporarily at Wts; combined bias.
    for (int i = tid; i < HDIM*5; i += NT) Wts[i] = Wih0[i];
    if (tid < HDIM) b2[tid] = bih0[tid] + bhh0[tid];
    __syncthreads();

    // Layer 0 input projection: Y[t][b][j] = bias[j] + sum_f x_t[b][f]*Wih0[j][f]
    for (int idx = tid; idx < TSEQ*NB*HDIM; idx += NT){
        int j  = idx & (HDIM-1);
        int bb = (idx >> 7) & (NB-1);
        int t  = idx >> 13;
        float a = b2[j];
        #pragma unroll
        for (int f = 0; f < 5; f++)
            a = fmaf(xs[bb*20 + f*4 + t], Wts[j*5 + f], a);
        Yf[(t*NB + bb)*SY + j] = a;
    }
    __syncthreads();

    load_wt(Whh0, Wts, tid);
    __syncthreads();
    recurrent_phase(Yf, Wts, tid, b0, j0);

    #pragma unroll 1
    for (int l = 0; l < NLAYER-1; l++){
        load_wt(WihS + l*HDIM*HDIM, Wts, tid);
        if (tid < HDIM) b2[tid] = bihS[l*HDIM + tid] + bhhS[l*HDIM + tid];
        __syncthreads();
        input_phase(Yf, Wts, b2, b0, j0);

        load_wt(WhhS + l*HDIM*HDIM, Wts, tid);
        __syncthreads();
        recurrent_phase(Yf, Wts, tid, b0, j0);
    }

    // Head: out[b] = dot(Y[3][b][:], Wfc) + bfc
    if (tid < HDIM) wfc[tid] = Wfc[tid];
    __syncthreads();
    int bb   = tid >> 2;
    int part = tid & 3;
    const float* hr = Yf + (3*NB + bb)*SY + part*32;
    const float* wr = wfc + part*32;
    float s = 0.0f;
    #pragma unroll
    for (int k = 0; k < 32; k++) s = fmaf(hr[k], wr[k], s);
    s += __shfl_xor_sync(0xffffffffu, s, 1);
    s += __shfl_xor_sync(0xffffffffu, s, 2);
    if (part == 0 && (baseb + bb) < Btot)
        out[baseb + bb] = s + bfc[0];
}

extern "C" void kernel_launch(void* const* d_in, const int* in_sizes, int n_in,
                              void* d_out, int out_size)
{
    const float* x    = (const float*)d_in[0];
    const float* Wih0 = (const float*)d_in[1];
    const float* Whh0 = (const float*)d_in[2];
    const float* bih0 = (const float*)d_in[3];
    const float* bhh0 = (const float*)d_in[4];
    const float* WihS = (const float*)d_in[5];
    const float* WhhS = (const float*)d_in[6];
    const float* bihS = (const float*)d_in[7];
    const float* bhhS = (const float*)d_in[8];
    const float* Wfc  = (const float*)d_in[9];
    const float* bfc  = (const float*)d_in[10];
    float* out = (float*)d_out;

    int Btot = in_sizes[0] / 20;              // x has 20 floats per batch row
    int grid = (Btot + NB - 1) / NB;          // 4096 for B=262144

    // Needed for >48KB dynamic SMEM; attribute set (not a stream op) is
    // graph-capture safe and idempotent.
    cudaFuncSetAttribute(rnn_kernel,
                         cudaFuncAttributeMaxDynamicSharedMemorySize, SMEM_BYTES);

    rnn_kernel<<<grid, NT, SMEM_BYTES>>>(x, Wih0, Whh0, bih0, bhh0,
                                         WihS, WhhS, bihS, bhhS,
                                         Wfc, bfc, out, Btot);
}

// round 2
// speedup vs baseline: 1.0003x; 1.0003x over previous
#include <cuda_runtime.h>

// RNNModel: B=262144, F=5, T=4, H=128, L=5 tanh RNN + scalar head.
// Strategy: one CTA per 64-row batch tile; all activations Y[4][64][128] in SMEM,
// weights staged (transposed) per phase into SMEM; fp32 register-tiled GEMMs.

#define NB    64          // batch rows per CTA
#define HDIM  128
#define TSEQ  4
#define SY    132         // padded row stride for Y (floats)
#define SW    132         // padded row stride for Wt (floats)
#define NT    256         // threads per CTA
#define NLAYER 5

// SMEM layout (float offsets)
#define OFF_Y    0
#define OFF_W    (TSEQ*NB*SY)            // 33792
#define OFF_XS   (OFF_W + HDIM*SW)       // + 16896 = 50688
#define OFF_B2   (OFF_XS + NB*20)        // + 1280  = 51968
#define OFF_WFC  (OFF_B2 + HDIM)         // + 128   = 52096
#define SMEM_FLOATS (OFF_WFC + HDIM)     // 52224
#define SMEM_BYTES  (SMEM_FLOATS * 4)    // 208896 bytes

// Accurate-enough tanh (~1e-6 rel err): 2 MUFU (ex2, rcp) + few ALU ops.
// Deliberately NOT tanh.approx.f32 (abs err ~6e-4 would compound over 20 steps).
__device__ __forceinline__ float fast_tanh(float x){
    float ax = fabsf(x);
    float e  = __expf(-2.0f * ax);
    float r  = __fdividef(1.0f - e, 1.0f + e);
    return copysignf(r, x);
}

// Load a 128x128 weight matrix g[j][k] (row-major) into SMEM transposed:
// w[k*SW + j]. GMEM reads coalesced (lane -> k); STS.128 along j (4-way conflict,
// minimum possible for a column store; ~4% of runtime total).
__device__ __forceinline__ void load_wt(const float* __restrict__ g,
                                        float* __restrict__ w, int tid){
    int lane = tid & 31, wp = tid >> 5;
    #pragma unroll 4
    for (int it = wp; it < 128; it += 8){      // 32 j-groups x 4 k-groups
        int jg = it >> 2, kg = it & 3;
        int j0 = jg * 4;
        int k  = kg * 32 + lane;
        float v0 = g[(j0+0)*HDIM + k];
        float v1 = g[(j0+1)*HDIM + k];
        float v2 = g[(j0+2)*HDIM + k];
        float v3 = g[(j0+3)*HDIM + k];
        *(float4*)(w + k*SW + j0) = make_float4(v0, v1, v2, v3);
    }
}

// C[b0..b0+3][j0..j0+7] += A[b][k] * Wt[k][j]  over k=0..127.
// A rows: float4 over k (warp-broadcast across tx). W: float4 over j (conflict-free).
__device__ __forceinline__ void gemm_tile(const float* __restrict__ A,
                                          const float* __restrict__ W,
                                          float acc[4][8], int b0, int j0){
    const float* a0 = A + (b0+0)*SY;
    const float* a1 = A + (b0+1)*SY;
    const float* a2 = A + (b0+2)*SY;
    const float* a3 = A + (b0+3)*SY;
    const float* wp = W + j0;
    #pragma unroll 2
    for (int k = 0; k < HDIM; k += 4){
        float4 va[4];
        va[0] = *(const float4*)(a0 + k);
        va[1] = *(const float4*)(a1 + k);
        va[2] = *(const float4*)(a2 + k);
        va[3] = *(const float4*)(a3 + k);
        #pragma unroll
        for (int kk = 0; kk < 4; kk++){
            float4 w0 = *(const float4*)(wp + (k+kk)*SW);
            float4 w1 = *(const float4*)(wp + (k+kk)*SW + 4);
            #pragma unroll
            for (int i = 0; i < 4; i++){
                float av = ((const float*)(va + i))[kk];
                acc[i][0] = fmaf(av, w0.x, acc[i][0]);
                acc[i][1] = fmaf(av, w0.y, acc[i][1]);
                acc[i][2] = fmaf(av, w0.z, acc[i][2]);
                acc[i][3] = fmaf(av, w0.w, acc[i][3]);
                acc[i][4] = fmaf(av, w1.x, acc[i][4]);
                acc[i][5] = fmaf(av, w1.y, acc[i][5]);
                acc[i][6] = fmaf(av, w1.z, acc[i][6]);
                acc[i][7] = fmaf(av, w1.w, acc[i][7]);
            }
        }
    }
}

__device__ __forceinline__ void store_tile(float* __restrict__ dst,
                                           const float acc[4][8], int b0, int j0){
    #pragma unroll
    for (int i = 0; i < 4; i++){
        *(float4*)(dst + (b0+i)*SY + j0)     = make_float4(acc[i][0],acc[i][1],acc[i][2],acc[i][3]);
        *(float4*)(dst + (b0+i)*SY + j0 + 4) = make_float4(acc[i][4],acc[i][5],acc[i][6],acc[i][7]);
    }
}

// Wts holds W_hh transposed. t=0: h = tanh(xin). t>=1: Y[t] = tanh(Y[t] + Y[t-1] @ Whh^T).
__device__ __forceinline__ void recurrent_phase(float* __restrict__ Yf,
                                                const float* __restrict__ Wts,
                                                int tid, int b0, int j0){
    for (int idx = tid; idx < NB*HDIM; idx += NT){
        int bb = idx >> 7, j = idx & (HDIM-1);
        float* p = Yf + bb*SY + j;
        *p = fast_tanh(*p);
    }
    __syncthreads();
    for (int t = 1; t < TSEQ; t++){
        float acc[4][8];
        #pragma unroll
        for (int i = 0; i < 4; i++){
            float4 p0 = *(const float4*)(Yf + (t*NB + b0 + i)*SY + j0);
            float4 p1 = *(const float4*)(Yf + (t*NB + b0 + i)*SY + j0 + 4);
            acc[i][0]=p0.x; acc[i][1]=p0.y; acc[i][2]=p0.z; acc[i][3]=p0.w;
            acc[i][4]=p1.x; acc[i][5]=p1.y; acc[i][6]=p1.z; acc[i][7]=p1.w;
        }
        gemm_tile(Yf + (t-1)*NB*SY, Wts, acc, b0, j0);
        #pragma unroll
        for (int i = 0; i < 4; i++)
            #pragma unroll
            for (int jj = 0; jj < 8; jj++) acc[i][jj] = fast_tanh(acc[i][jj]);
        __syncthreads();                    // all reads of Y[t-1] & Y[t] done
        store_tile(Yf + t*NB*SY, acc, b0, j0);
        __syncthreads();
    }
}

// Wts holds W_ih transposed. In-place: Y[t] = bias + Y[t] @ Wih^T.
// Safe: each output tile is fully in registers before the barrier + write-back.
__device__ __forceinline__ void input_phase(float* __restrict__ Yf,
                                            const float* __restrict__ Wts,
                                            const float* __restrict__ b2,
                                            int b0, int j0){
    float4 bb0 = *(const float4*)(b2 + j0);
    float4 bb1 = *(const float4*)(b2 + j0 + 4);
    for (int t = 0; t < TSEQ; t++){
        float acc[4][8];
        #pragma unroll
        for (int i = 0; i < 4; i++){
            acc[i][0]=bb0.x; acc[i][1]=bb0.y; acc[i][2]=bb0.z; acc[i][3]=bb0.w;
            acc[i][4]=bb1.x; acc[i][5]=bb1.y; acc[i][6]=bb1.z; acc[i][7]=bb1.w;
        }
        gemm_tile(Yf + t*NB*SY, Wts, acc, b0, j0);
        __syncthreads();
        store_tile(Yf + t*NB*SY, acc, b0, j0);
        __syncthreads();
    }
}

__global__ void __launch_bounds__(NT, 1)
rnn_kernel(const float* __restrict__ x,
           const float* __restrict__ Wih0, const float* __restrict__ Whh0,
           const float* __restrict__ bih0, const float* __restrict__ bhh0,
           const float* __restrict__ WihS, const float* __restrict__ WhhS,
           const float* __restrict__ bihS, const float* __restrict__ bhhS,
           const float* __restrict__ Wfc,  const float* __restrict__ bfc,
           float* __restrict__ out, int Btot)
{
    extern __shared__ float sm[];
    float* Yf  = sm + OFF_Y;
    float* Wts = sm + OFF_W;
    float* xs  = sm + OFF_XS;
    float* b2  = sm + OFF_B2;
    float* wfc = sm + OFF_WFC;

    const int tid = threadIdx.x;
    const int tx = tid & 15, ty = tid >> 4;
    const int b0 = ty * 4, j0 = tx * 8;
    const long long baseb = (long long)blockIdx.x * NB;

    // Stage x tile (b,f,t layout: x[b*20 + f*4 + t]); contiguous & coalesced.
    for (int i = tid; i < NB*20; i += NT){
        long long g = baseb*20 + i;
        xs[i] = (g < (long long)Btot*20) ? x[g] : 0.0f;
    }
    // Layer-0 input weights (128x5) temporarily at Wts; combined bias.
    for (int i = tid; i < HDIM*5; i += NT) Wts[i] = Wih0[i];
    if (tid < HDIM) b2[tid] = bih0[tid] + bhh0[tid];
    __syncthreads();

    // Layer 0 input projection: Y[t][b][j] = bias[j] + sum_f x_t[b][f]*Wih0[j][f]
    for (int idx = tid; idx < TSEQ*NB*HDIM; idx += NT){
        int j  = idx & (HDIM-1);
        int bb = (idx >> 7) & (NB-1);
        int t  = idx >> 13;
        float a = b2[j];
        #pragma unroll
        for (int f = 0; f < 5; f++)
            a = fmaf(xs[bb*20 + f*4 + t], Wts[j*5 + f], a);
        Yf[(t*NB + bb)*SY + j] = a;
    }
    __syncthreads();

    load_wt(Whh0, Wts, tid);
    __syncthreads();
    recurrent_phase(Yf, Wts, tid, b0, j0);

    #pragma unroll 1
    for (int l = 0; l < NLAYER-1; l++){
        load_wt(WihS + l*HDIM*HDIM, Wts, tid);
        if (tid < HDIM) b2[tid] = bihS[l*HDIM + tid] + bhhS[l*HDIM + tid];
        __syncthreads();
        input_phase(Yf, Wts, b2, b0, j0);

        load_wt(WhhS + l*HDIM*HDIM, Wts, tid);
        __syncthreads();
        recurrent_phase(Yf, Wts, tid, b0, j0);
    }

    // Head: out[b] = dot(Y[3][b][:], Wfc) + bfc
    if (tid < HDIM) wfc[tid] = Wfc[tid];
    __syncthreads();
    int bb   = tid >> 2;
    int part = tid & 3;
    const float* hr = Yf + (3*NB + bb)*SY + part*32;
    const float* wr = wfc + part*32;
    float s = 0.0f;
    #pragma unroll
    for (int k = 0; k < 32; k++) s = fmaf(hr[k], wr[k], s);
    s += __shfl_xor_sync(0xffffffffu, s, 1);
    s += __shfl_xor_sync(0xffffffffu, s, 2);
    if (part == 0 && (baseb + bb) < Btot)
        out[baseb + bb] = s + bfc[0];
}

extern "C" void kernel_launch(void* const* d_in, const int* in_sizes, int n_in,
                              void* d_out, int out_size)
{
    const float* x    = (const float*)d_in[0];
    const float* Wih0 = (const float*)d_in[1];
    const float* Whh0 = (const float*)d_in[2];
    const float* bih0 = (const float*)d_in[3];
    const float* bhh0 = (const float*)d_in[4];
    const float* WihS = (const float*)d_in[5];
    const float* WhhS = (const float*)d_in[6];
    const float* bihS = (const float*)d_in[7];
    const float* bhhS = (const float*)d_in[8];
    const float* Wfc  = (const float*)d_in[9];
    const float* bfc  = (const float*)d_in[10];
    float* out = (float*)d_out;

    int Btot = in_sizes[0] / 20;              // x has 20 floats per batch row
    int grid = (Btot + NB - 1) / NB;          // 4096 for B=262144

    // Needed for >48KB dynamic SMEM; attribute set (not a stream op) is
    // graph-capture safe and idempotent.
    cudaFuncSetAttribute(rnn_kernel,
                         cudaFuncAttributeMaxDynamicSharedMemorySize, SMEM_BYTES);

    rnn_kernel<<<grid, NT, SMEM_BYTES>>>(x, Wih0, Whh0, bih0, bhh0,
                                         WihS, WhhS, bihS, bhhS,
                                         Wfc, bfc, out, Btot);
}

// round 4
// speedup vs baseline: 3.3757x; 3.3746x over previous
#include <cuda_runtime.h>
#include <cuda_bf16.h>
#include <cstdint>

// ============================================================================
// RNNModel B=262144, F=5, T=4, H=128, L=5 — bf16 mma.sync split-precision.
// D[64b][128j] = h[64][128k] @ W^T ; A=h row-major, B=W[j][k] "col-major k x n".
// 3-term split: W=Wh+Wl, h=hh+hl; D = AhBh + AhBl + AlBh  (AlBl ~ 2^-18 dropped).
// All 4 timesteps' accumulators are register-resident, so only one weight
// matrix occupies SMEM at a time (passA: Wih, swap, passB: Whh).
// ============================================================================

#define HDIM 128
#define TSEQ 4
#define MB   64
#define NT   256
#define NLAYER 5

#define HPW  68          // padded row stride: 136 bf16 = 68 u32 words (conflict-free)
#define W_HALF_BYTES 34816   // 128*136*2
#define H_TILE_BYTES 17408   // 64*136*2

// ---- SMEM byte offsets ----
#define OFF_H     0                       // 4t x (hi 17408 + lo 17408) = 139264
#define H_PAIR    34816
#define OFF_W     139264                  // Whi 34816 + Wlo 34816 = 69632
#define OFF_X     208896                  // 4t x (hi 2048 + lo 2048) = 16384
#define X_PAIR    4096
#define OFF_B2    225280                  // 128 fp32
#define OFF_WFC   225792                  // 128 fp32
#define OFF_SPART 226304                  // 256 fp32
#define SMEM_BYTES 227328                 // <= 232448 max dynamic on sm_100

// ---- pre-split, pre-padded weights: slot 2l = W_ih(l), 2l+1 = W_hh(l) ----
// layout: [j][136] bf16 row-major, cols >= real K zero-filled.
__device__ __align__(16) __nv_bfloat16 g_Whi[10][17408];
__device__ __align__(16) __nv_bfloat16 g_Wlo[10][17408];

// m16n8k16 row.col bf16 MMA, fp32 accum (sm_80+ baseline PTX; valid on sm_100).
__device__ __forceinline__ void mma16816(float* c,
        uint32_t a0, uint32_t a1, uint32_t a2, uint32_t a3,
        uint32_t b0, uint32_t b1){
    asm volatile(
        "mma.sync.aligned.m16n8k16.row.col.f32.bf16.bf16.f32 "
        "{%0,%1,%2,%3}, {%4,%5,%6,%7}, {%8,%9}, {%0,%1,%2,%3};"
        : "+f"(c[0]), "+f"(c[1]), "+f"(c[2]), "+f"(c[3])
        : "r"(a0), "r"(a1), "r"(a2), "r"(a3), "r"(b0), "r"(b1));
}

__device__ __forceinline__ uint32_t pack_bf2(float lo, float hi){
    __nv_bfloat162 p = __floats2bfloat162_rn(lo, hi);   // .x -> low 16 bits
    return *(uint32_t*)&p;
}

// accurate tanh (~1e-7 abs). NOT tanh.approx (6e-4 would compound over 20 steps).
__device__ __forceinline__ float fast_tanh(float x){
    float ax = fabsf(x);
    float e  = __expf(-2.0f * ax);
    float r  = __fdividef(1.0f - e, 1.0f + e);
    return copysignf(r, x);
}

// ============================================================================
// Prep: split all 10 weight matrices into bf16 hi/lo, padded [j][136] rows.
// ============================================================================
__global__ void prep_weights(const float* __restrict__ Wih0,
                             const float* __restrict__ Whh0,
                             const float* __restrict__ WihS,
                             const float* __restrict__ WhhS){
    int slot = blockIdx.x;                  // 0..9
    for (int idx = threadIdx.x; idx < 17408; idx += blockDim.x){
        int j = idx / 136, k = idx % 136;
        float w = 0.0f;
        if (slot == 0)      { if (k < 5)   w = Wih0[j*5 + k]; }
        else if (slot == 1) { if (k < 128) w = Whh0[j*128 + k]; }
        else if (slot & 1)  { if (k < 128) w = WhhS[((slot>>1)-1)*16384 + j*128 + k]; }
        else                { if (k < 128) w = WihS[((slot>>1)-1)*16384 + j*128 + k]; }
        __nv_bfloat16 hi = __float2bfloat16(w);
        __nv_bfloat16 lo = __float2bfloat16(w - __bfloat162float(hi));
        g_Whi[slot][idx] = hi;
        g_Wlo[slot][idx] = lo;
    }
}

// copy one matrix (hi+lo halves) into the SMEM W region
__device__ __forceinline__ void copyW(int slot, char* smem, int tid){
    const uint4* sh = (const uint4*)g_Whi[slot];
    const uint4* sl = (const uint4*)g_Wlo[slot];
    uint4* dh = (uint4*)(smem + OFF_W);
    uint4* dl = (uint4*)(smem + OFF_W + W_HALF_BYTES);
    #pragma unroll 4
    for (int i = tid; i < 2176; i += NT){ dh[i] = sh[i]; dl[i] = sl[i]; }
}

// ============================================================================
__global__ void __launch_bounds__(NT)
rnn_mma(const float* __restrict__ x,
        const float* __restrict__ bih0, const float* __restrict__ bhh0,
        const float* __restrict__ bihS, const float* __restrict__ bhhS,
        const float* __restrict__ Wfc,  const float* __restrict__ bfc,
        float* __restrict__ out, int Btot)
{
    extern __shared__ __align__(16) char smem[];
    const int tid  = threadIdx.x;
    const int wid  = tid >> 5, lane = tid & 31;
    const int g    = lane >> 2, c = lane & 3;
    const int m0   = (wid & 1) * 32;        // warp's batch-row base
    const int n0   = (wid >> 1) * 32;       // warp's hidden-col base
    const long long baseb = (long long)blockIdx.x * MB;

    float* b2   = (float*)(smem + OFF_B2);
    float* wfc  = (float*)(smem + OFF_WFC);

    // ---- stage wfc + x tiles (bf16 hi/lo split, [64][16] k-padded) ----
    if (tid < 128) wfc[tid] = Wfc[tid];
    {
        int b = tid >> 2, t = tid & 3;
        long long gb = baseb + b;
        float xv[5];
        #pragma unroll
        for (int f = 0; f < 5; f++)
            xv[f] = (gb < Btot) ? x[gb*20 + f*4 + t] : 0.0f;
        uint32_t* xh = (uint32_t*)(smem + OFF_X + t*X_PAIR);
        uint32_t* xl = xh + 512;
        #pragma unroll
        for (int w = 0; w < 8; w++){
            float v0 = (2*w   < 5) ? xv[2*w]   : 0.0f;
            float v1 = (2*w+1 < 5) ? xv[2*w+1] : 0.0f;
            __nv_bfloat16 h0 = __float2bfloat16(v0);
            __nv_bfloat16 h1 = __float2bfloat16(v1);
            float r0 = v0 - __bfloat162float(h0);
            float r1 = v1 - __bfloat162float(h1);
            xh[b*8 + w] = pack_bf2(__bfloat162float(h0), __bfloat162float(h1)) ,
            xh[b*8 + w] = (uint32_t)(*(unsigned short*)&h0) | ((uint32_t)(*(unsigned short*)&h1) << 16);
            __nv_bfloat16 l0 = __float2bfloat16(r0);
            __nv_bfloat16 l1 = __float2bfloat16(r1);
            xl[b*8 + w] = (uint32_t)(*(unsigned short*)&l0) | ((uint32_t)(*(unsigned short*)&l1) << 16);
        }
    }

    float acc[128];     // [t][mf][nf][4] fully register-resident

    const uint32_t* wh = (const uint32_t*)(smem + OFF_W);
    const uint32_t* wl = wh + (W_HALF_BYTES >> 2);

    #pragma unroll 1
    for (int l = 0; l < NLAYER; l++){
        // ---- load W_ih(l) + combined bias; W region free (sync covers) ----
        __syncthreads();
        copyW(2*l, smem, tid);
        if (tid < 128)
            b2[tid] = (l == 0) ? bih0[tid] + bhh0[tid]
                               : bihS[(l-1)*128 + tid] + bhhS[(l-1)*128 + tid];
        __syncthreads();

        // ---- init acc with bias ----
        #pragma unroll
        for (int mf = 0; mf < 2; mf++)
            #pragma unroll
            for (int nf = 0; nf < 4; nf++){
                float bv0 = b2[n0 + nf*8 + c*2];
                float bv1 = b2[n0 + nf*8 + c*2 + 1];
                #pragma unroll
                for (int t = 0; t < 4; t++){
                    float* cc = &acc[((t*2 + mf)*4 + nf)*4];
                    cc[0] = bv0; cc[1] = bv1; cc[2] = bv0; cc[3] = bv1;
                }
            }

        // ---- pass A: acc[t] += Wih . h_prev[t]  (B-fragments reused over t) ----
        if (l == 0){
            // single K=16 step from x tiles
            uint32_t bh0[4], bh1[4], bl0[4], bl1[4];
            #pragma unroll
            for (int nf = 0; nf < 4; nf++){
                int jw = (n0 + nf*8 + g)*HPW + c;
                bh0[nf] = wh[jw]; bh1[nf] = wh[jw + 4];
                bl0[nf] = wl[jw]; bl1[nf] = wl[jw + 4];
            }
            #pragma unroll
            for (int t = 0; t < 4; t++){
                const uint32_t* xh = (const uint32_t*)(smem + OFF_X + t*X_PAIR);
                const uint32_t* xl = xh + 512;
                #pragma unroll
                for (int mf = 0; mf < 2; mf++){
                    int rw = (m0 + mf*16 + g)*8 + c;
                    uint32_t ah0 = xh[rw], ah1 = xh[rw + 64];
                    uint32_t ah2 = xh[rw + 4], ah3 = xh[rw + 68];
                    uint32_t al0 = xl[rw], al1 = xl[rw + 64];
                    uint32_t al2 = xl[rw + 4], al3 = xl[rw + 68];
                    #pragma unroll
                    for (int nf = 0; nf < 4; nf++){
                        float* cc = &acc[((t*2 + mf)*4 + nf)*4];
                        mma16816(cc, ah0,ah1,ah2,ah3, bh0[nf], bh1[nf]);
                        mma16816(cc, ah0,ah1,ah2,ah3, bl0[nf], bl1[nf]);
                        mma16816(cc, al0,al1,al2,al3, bh0[nf], bh1[nf]);
                    }
                }
            }
        } else {
            #pragma unroll 1
            for (int kk = 0; kk < 8; kk++){
                int kw = kk*8;
                uint32_t bh0[4], bh1[4], bl0[4], bl1[4];
                #pragma unroll
                for (int nf = 0; nf < 4; nf++){
                    int jw = (n0 + nf*8 + g)*HPW + kw + c;
                    bh0[nf] = wh[jw]; bh1[nf] = wh[jw + 4];
                    bl0[nf] = wl[jw]; bl1[nf] = wl[jw + 4];
                }
                #pragma unroll
                for (int t = 0; t < 4; t++){
                    const uint32_t* hh = (const uint32_t*)(smem + OFF_H + t*H_PAIR);
                    const uint32_t* hl = hh + (H_TILE_BYTES >> 2);
                    #pragma unroll
                    for (int mf = 0; mf < 2; mf++){
                        int rw = (m0 + mf*16 + g)*HPW + kw + c;
                        uint32_t ah0 = hh[rw], ah1 = hh[rw + 8*HPW];
                        uint32_t ah2 = hh[rw + 4], ah3 = hh[rw + 8*HPW + 4];
                        uint32_t al0 = hl[rw], al1 = hl[rw + 8*HPW];
                        uint32_t al2 = hl[rw + 4], al3 = hl[rw + 8*HPW + 4];
                        #pragma unroll
                        for (int nf = 0; nf < 4; nf++){
                            float* cc = &acc[((t*2 + mf)*4 + nf)*4];
                            mma16816(cc, ah0,ah1,ah2,ah3, bh0[nf], bh1[nf]);
                            mma16816(cc, ah0,ah1,ah2,ah3, bl0[nf], bl1[nf]);
                            mma16816(cc, al0,al1,al2,al3, bh0[nf], bh1[nf]);
                        }
                    }
                }
            }
        }

        // ---- swap W region to W_hh(l) ----
        __syncthreads();
        copyW(2*l + 1, smem, tid);
        __syncthreads();

        // ---- pass B: sequential timesteps ----
        #pragma unroll
        for (int t = 0; t < 4; t++){
            if (t > 0){
                const uint32_t* hh = (const uint32_t*)(smem + OFF_H + (t-1)*H_PAIR);
                const uint32_t* hl = hh + (H_TILE_BYTES >> 2);
                #pragma unroll 1
                for (int kk = 0; kk < 8; kk++){
                    int kw = kk*8;
                    uint32_t bh0[4], bh1[4], bl0[4], bl1[4];
                    #pragma unroll
                    for (int nf = 0; nf < 4; nf++){
                        int jw = (n0 + nf*8 + g)*HPW + kw + c;
                        bh0[nf] = wh[jw]; bh1[nf] = wh[jw + 4];
                        bl0[nf] = wl[jw]; bl1[nf] = wl[jw + 4];
                    }
                    #pragma unroll
                    for (int mf = 0; mf < 2; mf++){
                        int rw = (m0 + mf*16 + g)*HPW + kw + c;
                        uint32_t ah0 = hh[rw], ah1 = hh[rw + 8*HPW];
                        uint32_t ah2 = hh[rw + 4], ah3 = hh[rw + 8*HPW + 4];
                        uint32_t al0 = hl[rw], al1 = hl[rw + 8*HPW];
                        uint32_t al2 = hl[rw + 4], al3 = hl[rw + 8*HPW + 4];
                        #pragma unroll
                        for (int nf = 0; nf < 4; nf++){
                            float* cc = &acc[((t*2 + mf)*4 + nf)*4];
                            mma16816(cc, ah0,ah1,ah2,ah3, bh0[nf], bh1[nf]);
                            mma16816(cc, ah0,ah1,ah2,ah3, bl0[nf], bl1[nf]);
                            mma16816(cc, al0,al1,al2,al3, bh0[nf], bh1[nf]);
                        }
                    }
                }
            }
            // epilogue: h_t = tanh(acc[t]); split; store (in-place over h_prev[t])
            uint32_t* hh = (uint32_t*)(smem + OFF_H + t*H_PAIR);
            uint32_t* hl = hh + (H_TILE_BYTES >> 2);
            #pragma unroll
            for (int mf = 0; mf < 2; mf++)
                #pragma unroll
                for (int nf = 0; nf < 4; nf++){
                    float* cc = &acc[((t*2 + mf)*4 + nf)*4];
                    #pragma unroll
                    for (int p = 0; p < 2; p++){
                        int row = m0 + mf*16 + g + p*8;
                        float h0 = fast_tanh(cc[2*p]);
                        float h1 = fast_tanh(cc[2*p + 1]);
                        __nv_bfloat16 b0 = __float2bfloat16(h0);
                        __nv_bfloat16 b1 = __float2bfloat16(h1);
                        float r0 = h0 - __bfloat162float(b0);
                        float r1 = h1 - __bfloat162float(b1);
                        __nv_bfloat16 l0b = __float2bfloat16(r0);
                        __nv_bfloat16 l1b = __float2bfloat16(r1);
                        int widx = row*HPW + ((n0 + nf*8) >> 1) + c;
                        hh[widx] = (uint32_t)(*(unsigned short*)&b0)
                                 | ((uint32_t)(*(unsigned short*)&b1) << 16);
                        hl[widx] = (uint32_t)(*(unsigned short*)&l0b)
                                 | ((uint32_t)(*(unsigned short*)&l1b) << 16);
                    }
                }
            __syncthreads();
        }
    }

    // ---- head: out[b] = dot(h3[b], wfc) + bfc ----
    {
        int b = tid >> 2, q = tid & 3;
        const uint32_t* hh = (const uint32_t*)(smem + OFF_H + 3*H_PAIR);
        const uint32_t* hl = hh + (H_TILE_BYTES >> 2);
        float s = 0.0f;
        #pragma unroll
        for (int w = 0; w < 16; w++){
            int widx = b*HPW + q*16 + w;
            uint32_t uh = hh[widx], ul = hl[widx];
            __nv_bfloat162 vh = *(__nv_bfloat162*)&uh;
            __nv_bfloat162 vl = *(__nv_bfloat162*)&ul;
            int j = q*32 + 2*w;
            s = fmaf(__bfloat162float(vh.x) + __bfloat162float(vl.x), wfc[j],   s);
            s = fmaf(__bfloat162float(vh.y) + __bfloat162float(vl.y), wfc[j+1], s);
        }
        ((float*)(smem + OFF_SPART))[tid] = s;
    }
    __syncthreads();
    if (tid < 64){
        const float* sp = (const float*)(smem + OFF_SPART);
        long long gb = baseb + tid;
        if (gb < Btot)
            out[gb] = sp[tid*4] + sp[tid*4+1] + sp[tid*4+2] + sp[tid*4+3] + bfc[0];
    }
}

// ============================================================================
extern "C" void kernel_launch(void* const* d_in, const int* in_sizes, int n_in,
                              void* d_out, int out_size)
{
    const float* x    = (const float*)d_in[0];
    const float* Wih0 = (const float*)d_in[1];
    const float* Whh0 = (const float*)d_in[2];
    const float* bih0 = (const float*)d_in[3];
    const float* bhh0 = (const float*)d_in[4];
    const float* WihS = (const float*)d_in[5];
    const float* WhhS = (const float*)d_in[6];
    const float* bihS = (const float*)d_in[7];
    const float* bhhS = (const float*)d_in[8];
    const float* Wfc  = (const float*)d_in[9];
    const float* bfc  = (const float*)d_in[10];
    float* out = (float*)d_out;

    int Btot = in_sizes[0] / 20;
    int grid = (Btot + MB - 1) / MB;

    cudaFuncSetAttribute(rnn_mma,
                         cudaFuncAttributeMaxDynamicSharedMemorySize, SMEM_BYTES);

    prep_weights<<<10, 256>>>(Wih0, Whh0, WihS, WhhS);
    rnn_mma<<<grid, NT, SMEM_BYTES>>>(x, bih0, bhh0, bihS, bhhS,
                                      Wfc, bfc, out, Btot);
}

// round 6
// speedup vs baseline: 3.5181x; 1.0422x over previous
#include <cuda_runtime.h>
#include <cuda_bf16.h>
#include <cstdint>

// ============================================================================
// RNNModel B=262144, F=5, T=4, H=128, L=5 — bf16 mma.sync split-precision v2b.
// 3-term split (W=Wh+Wl, h=hh+hl; D = AhBh + AhBl + AlBh), ldmatrix fragment
// loads, 16 warps, two independent 32-row batch groups with named barriers.
// v2 bug fixed: k-chunk byte advance is 32 bytes (16 bf16), not 16.
// ============================================================================

#define HDIM 128
#define TSEQ 4
#define MB   64
#define NT   512
#define NLAYER 5

#define HPW  68                  // padded row stride in u32 words (136 bf16, 272 B)
#define ROWB 272                 // bytes per padded row
#define W_HALF_BYTES 34816       // 128*272
#define H_TILE_BYTES 17408       // 64*272

// ---- SMEM byte offsets ----
#define OFF_H     0                       // 4t x (hi 17408 + lo 17408) = 139264
#define H_PAIR    34816
#define OFF_W     139264                  // Whi 34816 + Wlo 34816 = 69632
#define OFF_X     208896                  // 4t x (hi 2048 + lo 2048) = 16384
#define X_PAIR    4096
#define OFF_B2    225280                  // 128 fp32
#define OFF_WFC   225792                  // 128 fp32
#define OFF_SPART 226304                  // 256 fp32
#define SMEM_BYTES 227328

// ---- pre-split, pre-padded weights: slot 2l = W_ih(l), 2l+1 = W_hh(l) ----
__device__ __align__(16) __nv_bfloat16 g_Whi[10][17408];
__device__ __align__(16) __nv_bfloat16 g_Wlo[10][17408];

__device__ __forceinline__ uint32_t smem_u32(const void* p){
    uint32_t a;
    asm("{ .reg .u64 t; cvta.to.shared.u64 t, %1; cvt.u32.u64 %0, t; }"
        : "=r"(a) : "l"(p));
    return a;
}

__device__ __forceinline__ void ldm4(uint32_t* r, uint32_t addr){
    asm volatile("ldmatrix.sync.aligned.m8n8.x4.shared.b16 {%0,%1,%2,%3}, [%4];"
        : "=r"(r[0]), "=r"(r[1]), "=r"(r[2]), "=r"(r[3]) : "r"(addr));
}

__device__ __forceinline__ void mma16816(float* c,
        uint32_t a0, uint32_t a1, uint32_t a2, uint32_t a3,
        uint32_t b0, uint32_t b1){
    asm volatile(
        "mma.sync.aligned.m16n8k16.row.col.f32.bf16.bf16.f32 "
        "{%0,%1,%2,%3}, {%4,%5,%6,%7}, {%8,%9}, {%0,%1,%2,%3};"
        : "+f"(c[0]), "+f"(c[1]), "+f"(c[2]), "+f"(c[3])
        : "r"(a0), "r"(a1), "r"(a2), "r"(a3), "r"(b0), "r"(b1));
}

#define GROUP_BAR(gid) \
    asm volatile("bar.sync %0, %1;" :: "r"((gid) + 1), "r"(256) : "memory")

// accurate tanh (~1e-7 abs). NOT tanh.approx (6e-4 would compound over 20 steps).
__device__ __forceinline__ float fast_tanh(float x){
    float ax = fabsf(x);
    float e  = __expf(-2.0f * ax);
    float r  = __fdividef(1.0f - e, 1.0f + e);
    return copysignf(r, x);
}

// ============================================================================
// Prep: split all 10 weight matrices into bf16 hi/lo, padded [j][136] rows.
// ============================================================================
__global__ void prep_weights(const float* __restrict__ Wih0,
                             const float* __restrict__ Whh0,
                             const float* __restrict__ WihS,
                             const float* __restrict__ WhhS){
    int slot = blockIdx.x;
    for (int idx = threadIdx.x; idx < 17408; idx += blockDim.x){
        int j = idx / 136, k = idx % 136;
        float w = 0.0f;
        if (slot == 0)      { if (k < 5)   w = Wih0[j*5 + k]; }
        else if (slot == 1) { if (k < 128) w = Whh0[j*128 + k]; }
        else if (slot & 1)  { if (k < 128) w = WhhS[((slot>>1)-1)*16384 + j*128 + k]; }
        else                { if (k < 128) w = WihS[((slot>>1)-1)*16384 + j*128 + k]; }
        __nv_bfloat16 hi = __float2bfloat16(w);
        __nv_bfloat16 lo = __float2bfloat16(w - __bfloat162float(hi));
        g_Whi[slot][idx] = hi;
        g_Wlo[slot][idx] = lo;
    }
}

__device__ __forceinline__ void copyW(int slot, char* smem, int tid){
    const uint4* sh = (const uint4*)g_Whi[slot];
    const uint4* sl = (const uint4*)g_Wlo[slot];
    uint4* dh = (uint4*)(smem + OFF_W);
    uint4* dl = (uint4*)(smem + OFF_W + W_HALF_BYTES);
    #pragma unroll 5
    for (int i = tid; i < 2176; i += NT){ dh[i] = sh[i]; dl[i] = sl[i]; }
}

// ============================================================================
__global__ void __launch_bounds__(NT)
rnn_mma(const float* __restrict__ x,
        const float* __restrict__ bih0, const float* __restrict__ bhh0,
        const float* __restrict__ bihS, const float* __restrict__ bhhS,
        const float* __restrict__ Wfc,  const float* __restrict__ bfc,
        float* __restrict__ out, int Btot)
{
    extern __shared__ __align__(16) char smem[];
    const uint32_t sb = smem_u32(smem);
    const int tid  = threadIdx.x;
    const int wid  = tid >> 5, lane = tid & 31;
    const int g    = lane >> 2, c = lane & 3;
    const int grp  = wid >> 3;               // batch group 0/1
    const int gw   = wid & 7;                // warp within group
    const int m0   = grp * 32 + (gw & 1) * 16;   // warp's batch-row base
    const int n0   = (gw >> 1) * 32;             // warp's hidden-col base
    const long long baseb = (long long)blockIdx.x * MB;

    float* b2  = (float*)(smem + OFF_B2);
    float* wfc = (float*)(smem + OFF_WFC);

    // ---- per-lane ldmatrix byte offsets (within a tile) ----
    // A (m16k16): tiles {r0-7,k0},{r8-15,k0},{r0-7,k8},{r8-15,k8}
    const int aRow = m0 + (lane & 7) + ((lane >> 3) & 1) * 8;
    const int aK8  = (lane >> 4) * 8;
    const uint32_t aOff = (uint32_t)(aRow * ROWB + aK8 * 2);
    // B pair (2 nf per x4): tiles {j0-7,k0},{j0-7,k8},{j8-15,k0},{j8-15,k8}
    const int bRow = (lane & 7) + (lane >> 4) * 8;
    const int bK8  = ((lane >> 3) & 1) * 8;
    const uint32_t bOff0 = (uint32_t)((n0 + bRow) * ROWB + bK8 * 2);        // nf0,nf1
    const uint32_t bOff1 = (uint32_t)((n0 + 16 + bRow) * ROWB + bK8 * 2);   // nf2,nf3

    // ---- stage wfc + x tiles (bf16 hi/lo split, [64][8 words]) ----
    if (tid < 128) wfc[tid] = Wfc[tid];
    if (tid < 256){
        int b = tid >> 2, t = tid & 3;
        long long gb = baseb + b;
        float xv[5];
        #pragma unroll
        for (int f = 0; f < 5; f++)
            xv[f] = (gb < Btot) ? x[gb*20 + f*4 + t] : 0.0f;
        uint32_t* xh = (uint32_t*)(smem + OFF_X + t*X_PAIR);
        uint32_t* xl = xh + 512;
        #pragma unroll
        for (int w = 0; w < 8; w++){
            float v0 = (2*w   < 5) ? xv[2*w]   : 0.0f;
            float v1 = (2*w+1 < 5) ? xv[2*w+1] : 0.0f;
            __nv_bfloat16 h0 = __float2bfloat16(v0);
            __nv_bfloat16 h1 = __float2bfloat16(v1);
            __nv_bfloat16 l0 = __float2bfloat16(v0 - __bfloat162float(h0));
            __nv_bfloat16 l1 = __float2bfloat16(v1 - __bfloat162float(h1));
            xh[b*8 + w] = (uint32_t)(*(unsigned short*)&h0) | ((uint32_t)(*(unsigned short*)&h1) << 16);
            xl[b*8 + w] = (uint32_t)(*(unsigned short*)&l0) | ((uint32_t)(*(unsigned short*)&l1) << 16);
        }
    }

    float acc[64];                           // [t][nf][4]
    const uint32_t whAddr = sb + OFF_W;
    const uint32_t wlAddr = sb + OFF_W + W_HALF_BYTES;
    const uint32_t* whW = (const uint32_t*)(smem + OFF_W);
    const uint32_t* wlW = whW + (W_HALF_BYTES >> 2);

    #pragma unroll 1
    for (int l = 0; l < NLAYER; l++){
        __syncthreads();                     // all reads of previous W done
        copyW(2*l, smem, tid);
        if (tid < 128)
            b2[tid] = (l == 0) ? bih0[tid] + bhh0[tid]
                               : bihS[(l-1)*128 + tid] + bhhS[(l-1)*128 + tid];
        __syncthreads();

        // ---- init acc with bias ----
        #pragma unroll
        for (int nf = 0; nf < 4; nf++){
            float bv0 = b2[n0 + nf*8 + c*2];
            float bv1 = b2[n0 + nf*8 + c*2 + 1];
            #pragma unroll
            for (int t = 0; t < 4; t++){
                float* cc = &acc[(t*4 + nf)*4];
                cc[0] = bv0; cc[1] = bv1; cc[2] = bv0; cc[3] = bv1;
            }
        }

        // ---- pass A: acc[t] += Wih . h_prev[t] (no barriers needed) ----
        if (l == 0){
            // one K=16 step from x tiles (scalar LDS; tiny)
            uint32_t bh[8], bl[8];
            #pragma unroll
            for (int nf = 0; nf < 4; nf++){
                int jw = (n0 + nf*8 + g)*HPW + c;
                bh[nf*2]   = whW[jw]; bh[nf*2+1] = whW[jw + 4];
                bl[nf*2]   = wlW[jw]; bl[nf*2+1] = wlW[jw + 4];
            }
            #pragma unroll
            for (int t = 0; t < 4; t++){
                const uint32_t* xh = (const uint32_t*)(smem + OFF_X + t*X_PAIR);
                const uint32_t* xl = xh + 512;
                int rw = (m0 + g)*8 + c;
                uint32_t ah0 = xh[rw], ah1 = xh[rw + 64];
                uint32_t ah2 = xh[rw + 4], ah3 = xh[rw + 68];
                uint32_t al0 = xl[rw], al1 = xl[rw + 64];
                uint32_t al2 = xl[rw + 4], al3 = xl[rw + 68];
                float* ct = &acc[t*16];
                #pragma unroll
                for (int nf = 0; nf < 4; nf++)
                    mma16816(ct + nf*4, ah0,ah1,ah2,ah3, bh[nf*2], bh[nf*2+1]);
                #pragma unroll
                for (int nf = 0; nf < 4; nf++)
                    mma16816(ct + nf*4, ah0,ah1,ah2,ah3, bl[nf*2], bl[nf*2+1]);
                #pragma unroll
                for (int nf = 0; nf < 4; nf++)
                    mma16816(ct + nf*4, al0,al1,al2,al3, bh[nf*2], bh[nf*2+1]);
            }
        } else {
            #pragma unroll 1
            for (int kk = 0; kk < 8; kk++){
                uint32_t kb = kk * 32;       // 16 bf16 = 32 BYTES per k-chunk (v2 bug: was 16)
                uint32_t bh[8], bl[8];
                ldm4(bh,     whAddr + bOff0 + kb);
                ldm4(bh + 4, whAddr + bOff1 + kb);
                ldm4(bl,     wlAddr + bOff0 + kb);
                ldm4(bl + 4, wlAddr + bOff1 + kb);
                #pragma unroll
                for (int t = 0; t < 4; t++){
                    uint32_t hAddr = sb + OFF_H + t*H_PAIR + aOff + kb;
                    uint32_t ah[4], al[4];
                    ldm4(ah, hAddr);
                    ldm4(al, hAddr + H_TILE_BYTES);
                    float* ct = &acc[t*16];
                    #pragma unroll
                    for (int nf = 0; nf < 4; nf++)
                        mma16816(ct + nf*4, ah[0],ah[1],ah[2],ah[3], bh[nf*2], bh[nf*2+1]);
                    #pragma unroll
                    for (int nf = 0; nf < 4; nf++)
                        mma16816(ct + nf*4, ah[0],ah[1],ah[2],ah[3], bl[nf*2], bl[nf*2+1]);
                    #pragma unroll
                    for (int nf = 0; nf < 4; nf++)
                        mma16816(ct + nf*4, al[0],al[1],al[2],al[3], bh[nf*2], bh[nf*2+1]);
                }
            }
        }

        // ---- swap W region to W_hh(l) ----
        __syncthreads();
        copyW(2*l + 1, smem, tid);
        __syncthreads();

        // ---- pass B: sequential timesteps; group-scoped barriers ----
        #pragma unroll
        for (int t = 0; t < 4; t++){
            if (t > 0){
                float* ct = &acc[t*16];
                #pragma unroll 1
                for (int kk = 0; kk < 8; kk++){
                    uint32_t kb = kk * 32;   // 16 bf16 = 32 BYTES (fixed)
                    uint32_t bh[8], bl[8];
                    ldm4(bh,     whAddr + bOff0 + kb);
                    ldm4(bh + 4, whAddr + bOff1 + kb);
                    ldm4(bl,     wlAddr + bOff0 + kb);
                    ldm4(bl + 4, wlAddr + bOff1 + kb);
                    uint32_t hAddr = sb + OFF_H + (t-1)*H_PAIR + aOff + kb;
                    uint32_t ah[4], al[4];
                    ldm4(ah, hAddr);
                    ldm4(al, hAddr + H_TILE_BYTES);
                    #pragma unroll
                    for (int nf = 0; nf < 4; nf++)
                        mma16816(ct + nf*4, ah[0],ah[1],ah[2],ah[3], bh[nf*2], bh[nf*2+1]);
                    #pragma unroll
                    for (int nf = 0; nf < 4; nf++)
                        mma16816(ct + nf*4, ah[0],ah[1],ah[2],ah[3], bl[nf*2], bl[nf*2+1]);
                    #pragma unroll
                    for (int nf = 0; nf < 4; nf++)
                        mma16816(ct + nf*4, al[0],al[1],al[2],al[3], bh[nf*2], bh[nf*2+1]);
                }
            }
            // epilogue: h_t = tanh(acc[t]); split; store (in-place)
            uint32_t* hh = (uint32_t*)(smem + OFF_H + t*H_PAIR);
            uint32_t* hl = hh + (H_TILE_BYTES >> 2);
            #pragma unroll
            for (int nf = 0; nf < 4; nf++){
                float* cc = &acc[(t*4 + nf)*4];
                #pragma unroll
                for (int p = 0; p < 2; p++){
                    int row = m0 + g + p*8;
                    float h0 = fast_tanh(cc[2*p]);
                    float h1 = fast_tanh(cc[2*p + 1]);
                    __nv_bfloat16 hb0 = __float2bfloat16(h0);
                    __nv_bfloat16 hb1 = __float2bfloat16(h1);
                    __nv_bfloat16 lb0 = __float2bfloat16(h0 - __bfloat162float(hb0));
                    __nv_bfloat16 lb1 = __float2bfloat16(h1 - __bfloat162float(hb1));
                    int widx = row*HPW + ((n0 + nf*8) >> 1) + c;
                    hh[widx] = (uint32_t)(*(unsigned short*)&hb0)
                             | ((uint32_t)(*(unsigned short*)&hb1) << 16);
                    hl[widx] = (uint32_t)(*(unsigned short*)&lb0)
                             | ((uint32_t)(*(unsigned short*)&lb1) << 16);
                }
            }
            GROUP_BAR(grp);                  // h[t] visible within this batch group
        }
    }

    __syncthreads();                         // both groups' h[3] complete

    // ---- head: out[b] = dot(h3[b], wfc) + bfc ----
    if (tid < 256){
        int b = tid >> 2, q = tid & 3;
        const uint32_t* hh = (const uint32_t*)(smem + OFF_H + 3*H_PAIR);
        const uint32_t* hl = hh + (H_TILE_BYTES >> 2);
        float s = 0.0f;
        #pragma unroll
        for (int w = 0; w < 16; w++){
            int widx = b*HPW + q*16 + w;
            uint32_t uh = hh[widx], ul = hl[widx];
            __nv_bfloat162 vh = *(__nv_bfloat162*)&uh;
            __nv_bfloat162 vl = *(__nv_bfloat162*)&ul;
            int j = q*32 + 2*w;
            s = fmaf(__bfloat162float(vh.x) + __bfloat162float(vl.x), wfc[j],   s);
            s = fmaf(__bfloat162float(vh.y) + __bfloat162float(vl.y), wfc[j+1], s);
        }
        ((float*)(smem + OFF_SPART))[tid] = s;
    }
    __syncthreads();
    if (tid < 64){
        const float* sp = (const float*)(smem + OFF_SPART);
        long long gb = baseb + tid;
        if (gb < Btot)
            out[gb] = sp[tid*4] + sp[tid*4+1] + sp[tid*4+2] + sp[tid*4+3] + bfc[0];
    }
}

// ============================================================================
extern "C" void kernel_launch(void* const* d_in, const int* in_sizes, int n_in,
                              void* d_out, int out_size)
{
    const float* x    = (const float*)d_in[0];
    const float* Wih0 = (const float*)d_in[1];
    const float* Whh0 = (const float*)d_in[2];
    const float* bih0 = (const float*)d_in[3];
    const float* bhh0 = (const float*)d_in[4];
    const float* WihS = (const float*)d_in[5];
    const float* WhhS = (const float*)d_in[6];
    const float* bihS = (const float*)d_in[7];
    const float* bhhS = (const float*)d_in[8];
    const float* Wfc  = (const float*)d_in[9];
    const float* bfc  = (const float*)d_in[10];
    float* out = (float*)d_out;

    int Btot = in_sizes[0] / 20;
    int grid = (Btot + MB - 1) / MB;

    cudaFuncSetAttribute(rnn_mma,
                         cudaFuncAttributeMaxDynamicSharedMemorySize, SMEM_BYTES);

    prep_weights<<<10, 256>>>(Wih0, Whh0, WihS, WhhS);
    rnn_mma<<<grid, NT, SMEM_BYTES>>>(x, bih0, bhh0, bihS, bhhS,
                                      Wfc, bfc, out, Btot);
}

// round 7
// speedup vs baseline: 3.5236x; 1.0015x over previous
#include <cuda_runtime.h>
#include <cuda_bf16.h>
#include <cstdint>

// ============================================================================
// RNNModel B=262144, F=5, T=4, H=128, L=5 — bf16 mma.sync split-precision v2b.
// 3-term split (W=Wh+Wl, h=hh+hl; D = AhBh + AhBl + AlBh), ldmatrix fragment
// loads, 16 warps, two independent 32-row batch groups with named barriers.
// v2 bug fixed: k-chunk byte advance is 32 bytes (16 bf16), not 16.
// ============================================================================

#define HDIM 128
#define TSEQ 4
#define MB   64
#define NT   512
#define NLAYER 5

#define HPW  68                  // padded row stride in u32 words (136 bf16, 272 B)
#define ROWB 272                 // bytes per padded row
#define W_HALF_BYTES 34816       // 128*272
#define H_TILE_BYTES 17408       // 64*272

// ---- SMEM byte offsets ----
#define OFF_H     0                       // 4t x (hi 17408 + lo 17408) = 139264
#define H_PAIR    34816
#define OFF_W     139264                  // Whi 34816 + Wlo 34816 = 69632
#define OFF_X     208896                  // 4t x (hi 2048 + lo 2048) = 16384
#define X_PAIR    4096
#define OFF_B2    225280                  // 128 fp32
#define OFF_WFC   225792                  // 128 fp32
#define OFF_SPART 226304                  // 256 fp32
#define SMEM_BYTES 227328

// ---- pre-split, pre-padded weights: slot 2l = W_ih(l), 2l+1 = W_hh(l) ----
__device__ __align__(16) __nv_bfloat16 g_Whi[10][17408];
__device__ __align__(16) __nv_bfloat16 g_Wlo[10][17408];

__device__ __forceinline__ uint32_t smem_u32(const void* p){
    uint32_t a;
    asm("{ .reg .u64 t; cvta.to.shared.u64 t, %1; cvt.u32.u64 %0, t; }"
        : "=r"(a) : "l"(p));
    return a;
}

__device__ __forceinline__ void ldm4(uint32_t* r, uint32_t addr){
    asm volatile("ldmatrix.sync.aligned.m8n8.x4.shared.b16 {%0,%1,%2,%3}, [%4];"
        : "=r"(r[0]), "=r"(r[1]), "=r"(r[2]), "=r"(r[3]) : "r"(addr));
}

__device__ __forceinline__ void mma16816(float* c,
        uint32_t a0, uint32_t a1, uint32_t a2, uint32_t a3,
        uint32_t b0, uint32_t b1){
    asm volatile(
        "mma.sync.aligned.m16n8k16.row.col.f32.bf16.bf16.f32 "
        "{%0,%1,%2,%3}, {%4,%5,%6,%7}, {%8,%9}, {%0,%1,%2,%3};"
        : "+f"(c[0]), "+f"(c[1]), "+f"(c[2]), "+f"(c[3])
        : "r"(a0), "r"(a1), "r"(a2), "r"(a3), "r"(b0), "r"(b1));
}

#define GROUP_BAR(gid) \
    asm volatile("bar.sync %0, %1;" :: "r"((gid) + 1), "r"(256) : "memory")

// accurate tanh (~1e-7 abs). NOT tanh.approx (6e-4 would compound over 20 steps).
__device__ __forceinline__ float fast_tanh(float x){
    float ax = fabsf(x);
    float e  = __expf(-2.0f * ax);
    float r  = __fdividef(1.0f - e, 1.0f + e);
    return copysignf(r, x);
}

// ============================================================================
// Prep: split all 10 weight matrices into bf16 hi/lo, padded [j][136] rows.
// ============================================================================
__global__ void prep_weights(const float* __restrict__ Wih0,
                             const float* __restrict__ Whh0,
                             const float* __restrict__ WihS,
                             const float* __restrict__ WhhS){
    int slot = blockIdx.x;
    for (int idx = threadIdx.x; idx < 17408; idx += blockDim.x){
        int j = idx / 136, k = idx % 136;
        float w = 0.0f;
        if (slot == 0)      { if (k < 5)   w = Wih0[j*5 + k]; }
        else if (slot == 1) { if (k < 128) w = Whh0[j*128 + k]; }
        else if (slot & 1)  { if (k < 128) w = WhhS[((slot>>1)-1)*16384 + j*128 + k]; }
        else                { if (k < 128) w = WihS[((slot>>1)-1)*16384 + j*128 + k]; }
        __nv_bfloat16 hi = __float2bfloat16(w);
        __nv_bfloat16 lo = __float2bfloat16(w - __bfloat162float(hi));
        g_Whi[slot][idx] = hi;
        g_Wlo[slot][idx] = lo;
    }
}

__device__ __forceinline__ void copyW(int slot, char* smem, int tid){
    const uint4* sh = (const uint4*)g_Whi[slot];
    const uint4* sl = (const uint4*)g_Wlo[slot];
    uint4* dh = (uint4*)(smem + OFF_W);
    uint4* dl = (uint4*)(smem + OFF_W + W_HALF_BYTES);
    #pragma unroll 5
    for (int i = tid; i < 2176; i += NT){ dh[i] = sh[i]; dl[i] = sl[i]; }
}

// ============================================================================
__global__ void __launch_bounds__(NT)
rnn_mma(const float* __restrict__ x,
        const float* __restrict__ bih0, const float* __restrict__ bhh0,
        const float* __restrict__ bihS, const float* __restrict__ bhhS,
        const float* __restrict__ Wfc,  const float* __restrict__ bfc,
        float* __restrict__ out, int Btot)
{
    extern __shared__ __align__(16) char smem[];
    const uint32_t sb = smem_u32(smem);
    const int tid  = threadIdx.x;
    const int wid  = tid >> 5, lane = tid & 31;
    const int g    = lane >> 2, c = lane & 3;
    const int grp  = wid >> 3;               // batch group 0/1
    const int gw   = wid & 7;                // warp within group
    const int m0   = grp * 32 + (gw & 1) * 16;   // warp's batch-row base
    const int n0   = (gw >> 1) * 32;             // warp's hidden-col base
    const long long baseb = (long long)blockIdx.x * MB;

    float* b2  = (float*)(smem + OFF_B2);
    float* wfc = (float*)(smem + OFF_WFC);

    // ---- per-lane ldmatrix byte offsets (within a tile) ----
    // A (m16k16): tiles {r0-7,k0},{r8-15,k0},{r0-7,k8},{r8-15,k8}
    const int aRow = m0 + (lane & 7) + ((lane >> 3) & 1) * 8;
    const int aK8  = (lane >> 4) * 8;
    const uint32_t aOff = (uint32_t)(aRow * ROWB + aK8 * 2);
    // B pair (2 nf per x4): tiles {j0-7,k0},{j0-7,k8},{j8-15,k0},{j8-15,k8}
    const int bRow = (lane & 7) + (lane >> 4) * 8;
    const int bK8  = ((lane >> 3) & 1) * 8;
    const uint32_t bOff0 = (uint32_t)((n0 + bRow) * ROWB + bK8 * 2);        // nf0,nf1
    const uint32_t bOff1 = (uint32_t)((n0 + 16 + bRow) * ROWB + bK8 * 2);   // nf2,nf3

    // ---- stage wfc + x tiles (bf16 hi/lo split, [64][8 words]) ----
    if (tid < 128) wfc[tid] = Wfc[tid];
    if (tid < 256){
        int b = tid >> 2, t = tid & 3;
        long long gb = baseb + b;
        float xv[5];
        #pragma unroll
        for (int f = 0; f < 5; f++)
            xv[f] = (gb < Btot) ? x[gb*20 + f*4 + t] : 0.0f;
        uint32_t* xh = (uint32_t*)(smem + OFF_X + t*X_PAIR);
        uint32_t* xl = xh + 512;
        #pragma unroll
        for (int w = 0; w < 8; w++){
            float v0 = (2*w   < 5) ? xv[2*w]   : 0.0f;
            float v1 = (2*w+1 < 5) ? xv[2*w+1] : 0.0f;
            __nv_bfloat16 h0 = __float2bfloat16(v0);
            __nv_bfloat16 h1 = __float2bfloat16(v1);
            __nv_bfloat16 l0 = __float2bfloat16(v0 - __bfloat162float(h0));
            __nv_bfloat16 l1 = __float2bfloat16(v1 - __bfloat162float(h1));
            xh[b*8 + w] = (uint32_t)(*(unsigned short*)&h0) | ((uint32_t)(*(unsigned short*)&h1) << 16);
            xl[b*8 + w] = (uint32_t)(*(unsigned short*)&l0) | ((uint32_t)(*(unsigned short*)&l1) << 16);
        }
    }

    float acc[64];                           // [t][nf][4]
    const uint32_t whAddr = sb + OFF_W;
    const uint32_t wlAddr = sb + OFF_W + W_HALF_BYTES;
    const uint32_t* whW = (const uint32_t*)(smem + OFF_W);
    const uint32_t* wlW = whW + (W_HALF_BYTES >> 2);

    #pragma unroll 1
    for (int l = 0; l < NLAYER; l++){
        __syncthreads();                     // all reads of previous W done
        copyW(2*l, smem, tid);
        if (tid < 128)
            b2[tid] = (l == 0) ? bih0[tid] + bhh0[tid]
                               : bihS[(l-1)*128 + tid] + bhhS[(l-1)*128 + tid];
        __syncthreads();

        // ---- init acc with bias ----
        #pragma unroll
        for (int nf = 0; nf < 4; nf++){
            float bv0 = b2[n0 + nf*8 + c*2];
            float bv1 = b2[n0 + nf*8 + c*2 + 1];
            #pragma unroll
            for (int t = 0; t < 4; t++){
                float* cc = &acc[(t*4 + nf)*4];
                cc[0] = bv0; cc[1] = bv1; cc[2] = bv0; cc[3] = bv1;
            }
        }

        // ---- pass A: acc[t] += Wih . h_prev[t] (no barriers needed) ----
        if (l == 0){
            // one K=16 step from x tiles (scalar LDS; tiny)
            uint32_t bh[8], bl[8];
            #pragma unroll
            for (int nf = 0; nf < 4; nf++){
                int jw = (n0 + nf*8 + g)*HPW + c;
                bh[nf*2]   = whW[jw]; bh[nf*2+1] = whW[jw + 4];
                bl[nf*2]   = wlW[jw]; bl[nf*2+1] = wlW[jw + 4];
            }
            #pragma unroll
            for (int t = 0; t < 4; t++){
                const uint32_t* xh = (const uint32_t*)(smem + OFF_X + t*X_PAIR);
                const uint32_t* xl = xh + 512;
                int rw = (m0 + g)*8 + c;
                uint32_t ah0 = xh[rw], ah1 = xh[rw + 64];
                uint32_t ah2 = xh[rw + 4], ah3 = xh[rw + 68];
                uint32_t al0 = xl[rw], al1 = xl[rw + 64];
                uint32_t al2 = xl[rw + 4], al3 = xl[rw + 68];
                float* ct = &acc[t*16];
                #pragma unroll
                for (int nf = 0; nf < 4; nf++)
                    mma16816(ct + nf*4, ah0,ah1,ah2,ah3, bh[nf*2], bh[nf*2+1]);
                #pragma unroll
                for (int nf = 0; nf < 4; nf++)
                    mma16816(ct + nf*4, ah0,ah1,ah2,ah3, bl[nf*2], bl[nf*2+1]);
                #pragma unroll
                for (int nf = 0; nf < 4; nf++)
                    mma16816(ct + nf*4, al0,al1,al2,al3, bh[nf*2], bh[nf*2+1]);
            }
        } else {
            #pragma unroll 1
            for (int kk = 0; kk < 8; kk++){
                uint32_t kb = kk * 32;       // 16 bf16 = 32 BYTES per k-chunk (v2 bug: was 16)
                uint32_t bh[8], bl[8];
                ldm4(bh,     whAddr + bOff0 + kb);
                ldm4(bh + 4, whAddr + bOff1 + kb);
                ldm4(bl,     wlAddr + bOff0 + kb);
                ldm4(bl + 4, wlAddr + bOff1 + kb);
                #pragma unroll
                for (int t = 0; t < 4; t++){
                    uint32_t hAddr = sb + OFF_H + t*H_PAIR + aOff + kb;
                    uint32_t ah[4], al[4];
                    ldm4(ah, hAddr);
                    ldm4(al, hAddr + H_TILE_BYTES);
                    float* ct = &acc[t*16];
                    #pragma unroll
                    for (int nf = 0; nf < 4; nf++)
                        mma16816(ct + nf*4, ah[0],ah[1],ah[2],ah[3], bh[nf*2], bh[nf*2+1]);
                    #pragma unroll
                    for (int nf = 0; nf < 4; nf++)
                        mma16816(ct + nf*4, ah[0],ah[1],ah[2],ah[3], bl[nf*2], bl[nf*2+1]);
                    #pragma unroll
                    for (int nf = 0; nf < 4; nf++)
                        mma16816(ct + nf*4, al[0],al[1],al[2],al[3], bh[nf*2], bh[nf*2+1]);
                }
            }
        }

        // ---- swap W region to W_hh(l) ----
        __syncthreads();
        copyW(2*l + 1, smem, tid);
        __syncthreads();

        // ---- pass B: sequential timesteps; group-scoped barriers ----
        #pragma unroll
        for (int t = 0; t < 4; t++){
            if (t > 0){
                float* ct = &acc[t*16];
                #pragma unroll 1
                for (int kk = 0; kk < 8; kk++){
                    uint32_t kb = kk * 32;   // 16 bf16 = 32 BYTES (fixed)
                    uint32_t bh[8], bl[8];
                    ldm4(bh,     whAddr + bOff0 + kb);
                    ldm4(bh + 4, whAddr + bOff1 + kb);
                    ldm4(bl,     wlAddr + bOff0 + kb);
                    ldm4(bl + 4, wlAddr + bOff1 + kb);
                    uint32_t hAddr = sb + OFF_H + (t-1)*H_PAIR + aOff + kb;
                    uint32_t ah[4], al[4];
                    ldm4(ah, hAddr);
                    ldm4(al, hAddr + H_TILE_BYTES);
                    #pragma unroll
                    for (int nf = 0; nf < 4; nf++)
                        mma16816(ct + nf*4, ah[0],ah[1],ah[2],ah[3], bh[nf*2], bh[nf*2+1]);
                    #pragma unroll
                    for (int nf = 0; nf < 4; nf++)
                        mma16816(ct + nf*4, ah[0],ah[1],ah[2],ah[3], bl[nf*2], bl[nf*2+1]);
                    #pragma unroll
                    for (int nf = 0; nf < 4; nf++)
                        mma16816(ct + nf*4, al[0],al[1],al[2],al[3], bh[nf*2], bh[nf*2+1]);
                }
            }
            // epilogue: h_t = tanh(acc[t]); split; store (in-place)
            uint32_t* hh = (uint32_t*)(smem + OFF_H + t*H_PAIR);
            uint32_t* hl = hh + (H_TILE_BYTES >> 2);
            #pragma unroll
            for (int nf = 0; nf < 4; nf++){
                float* cc = &acc[(t*4 + nf)*4];
                #pragma unroll
                for (int p = 0; p < 2; p++){
                    int row = m0 + g + p*8;
                    float h0 = fast_tanh(cc[2*p]);
                    float h1 = fast_tanh(cc[2*p + 1]);
                    __nv_bfloat16 hb0 = __float2bfloat16(h0);
                    __nv_bfloat16 hb1 = __float2bfloat16(h1);
                    __nv_bfloat16 lb0 = __float2bfloat16(h0 - __bfloat162float(hb0));
                    __nv_bfloat16 lb1 = __float2bfloat16(h1 - __bfloat162float(hb1));
                    int widx = row*HPW + ((n0 + nf*8) >> 1) + c;
                    hh[widx] = (uint32_t)(*(unsigned short*)&hb0)
                             | ((uint32_t)(*(unsigned short*)&hb1) << 16);
                    hl[widx] = (uint32_t)(*(unsigned short*)&lb0)
                             | ((uint32_t)(*(unsigned short*)&lb1) << 16);
                }
            }
            GROUP_BAR(grp);                  // h[t] visible within this batch group
        }
    }

    __syncthreads();                         // both groups' h[3] complete

    // ---- head: out[b] = dot(h3[b], wfc) + bfc ----
    if (tid < 256){
        int b = tid >> 2, q = tid & 3;
        const uint32_t* hh = (const uint32_t*)(smem + OFF_H + 3*H_PAIR);
        const uint32_t* hl = hh + (H_TILE_BYTES >> 2);
        float s = 0.0f;
        #pragma unroll
        for (int w = 0; w < 16; w++){
            int widx = b*HPW + q*16 + w;
            uint32_t uh = hh[widx], ul = hl[widx];
            __nv_bfloat162 vh = *(__nv_bfloat162*)&uh;
            __nv_bfloat162 vl = *(__nv_bfloat162*)&ul;
            int j = q*32 + 2*w;
            s = fmaf(__bfloat162float(vh.x) + __bfloat162float(vl.x), wfc[j],   s);
            s = fmaf(__bfloat162float(vh.y) + __bfloat162float(vl.y), wfc[j+1], s);
        }
        ((float*)(smem + OFF_SPART))[tid] = s;
    }
    __syncthreads();
    if (tid < 64){
        const float* sp = (const float*)(smem + OFF_SPART);
        long long gb = baseb + tid;
        if (gb < Btot)
            out[gb] = sp[tid*4] + sp[tid*4+1] + sp[tid*4+2] + sp[tid*4+3] + bfc[0];
    }
}

// ============================================================================
extern "C" void kernel_launch(void* const* d_in, const int* in_sizes, int n_in,
                              void* d_out, int out_size)
{
    const float* x    = (const float*)d_in[0];
    const float* Wih0 = (const float*)d_in[1];
    const float* Whh0 = (const float*)d_in[2];
    const float* bih0 = (const float*)d_in[3];
    const float* bhh0 = (const float*)d_in[4];
    const float* WihS = (const float*)d_in[5];
    const float* WhhS = (const float*)d_in[6];
    const float* bihS = (const float*)d_in[7];
    const float* bhhS = (const float*)d_in[8];
    const float* Wfc  = (const float*)d_in[9];
    const float* bfc  = (const float*)d_in[10];
    float* out = (float*)d_out;

    int Btot = in_sizes[0] / 20;
    int grid = (Btot + MB - 1) / MB;

    cudaFuncSetAttribute(rnn_mma,
                         cudaFuncAttributeMaxDynamicSharedMemorySize, SMEM_BYTES);

    prep_weights<<<10, 256>>>(Wih0, Whh0, WihS, WhhS);
    rnn_mma<<<grid, NT, SMEM_BYTES>>>(x, bih0, bhh0, bihS, bhhS,
                                      Wfc, bfc, out, Btot);
}

// round 9
// speedup vs baseline: 4.0900x; 1.1608x over previous
#include <cuda_runtime.h>
#include <cuda_bf16.h>
#include <cstdint>

// ============================================================================
// RNNModel B=262144, F=5, T=4, H=128, L=5 — bf16 mma.sync split-precision v3.
// 3-term split (W=Wh+Wl, h=hh+hl; D = AhBh + AhBl + AlBh), ldmatrix fragment
// loads. v3: FOUR batch groups of 4 warps (grp = wid>>2 so each group spans
// all 4 SMSPs and each SMSP hosts 4 independent recurrent chains), t=3 group
// barrier dropped, W swaps via cp.async.
// ============================================================================

#define HDIM 128
#define TSEQ 4
#define MB   64
#define NT   512
#define NLAYER 5

#define HPW  68                  // padded row stride in u32 words (136 bf16, 272 B)
#define ROWB 272                 // bytes per padded row
#define W_HALF_BYTES 34816       // 128*272
#define H_TILE_BYTES 17408       // 64*272

// ---- SMEM byte offsets ----
#define OFF_H     0                       // 4t x (hi 17408 + lo 17408) = 139264
#define H_PAIR    34816
#define OFF_W     139264                  // Whi 34816 + Wlo 34816 = 69632
#define OFF_X     208896                  // 4t x (hi 2048 + lo 2048) = 16384
#define X_PAIR    4096
#define OFF_B2    225280                  // 128 fp32
#define OFF_WFC   225792                  // 128 fp32
#define OFF_SPART 226304                  // 256 fp32
#define SMEM_BYTES 227328

// ---- pre-split, pre-padded weights: slot 2l = W_ih(l), 2l+1 = W_hh(l) ----
__device__ __align__(16) __nv_bfloat16 g_Whi[10][17408];
__device__ __align__(16) __nv_bfloat16 g_Wlo[10][17408];

__device__ __forceinline__ uint32_t smem_u32(const void* p){
    uint32_t a;
    asm("{ .reg .u64 t; cvta.to.shared.u64 t, %1; cvt.u32.u64 %0, t; }"
        : "=r"(a) : "l"(p));
    return a;
}

__device__ __forceinline__ void ldm4(uint32_t* r, uint32_t addr){
    asm volatile("ldmatrix.sync.aligned.m8n8.x4.shared.b16 {%0,%1,%2,%3}, [%4];"
        : "=r"(r[0]), "=r"(r[1]), "=r"(r[2]), "=r"(r[3]) : "r"(addr));
}

__device__ __forceinline__ void mma16816(float* c,
        uint32_t a0, uint32_t a1, uint32_t a2, uint32_t a3,
        uint32_t b0, uint32_t b1){
    asm volatile(
        "mma.sync.aligned.m16n8k16.row.col.f32.bf16.bf16.f32 "
        "{%0,%1,%2,%3}, {%4,%5,%6,%7}, {%8,%9}, {%0,%1,%2,%3};"
        : "+f"(c[0]), "+f"(c[1]), "+f"(c[2]), "+f"(c[3])
        : "r"(a0), "r"(a1), "r"(a2), "r"(a3), "r"(b0), "r"(b1));
}

#define GROUP_BAR(gid) \
    asm volatile("bar.sync %0, %1;" :: "r"((gid) + 1), "r"(128) : "memory")

__device__ __forceinline__ void cp_async16(uint32_t dst, const void* src){
    asm volatile("cp.async.cg.shared.global [%0], [%1], 16;"
                 :: "r"(dst), "l"(src) : "memory");
}
#define CP_ASYNC_COMMIT() asm volatile("cp.async.commit_group;" ::: "memory")
#define CP_ASYNC_WAIT()   asm volatile("cp.async.wait_group 0;" ::: "memory")

// accurate tanh (~1e-7 abs). NOT tanh.approx (6e-4 would compound over 20 steps).
__device__ __forceinline__ float fast_tanh(float x){
    float ax = fabsf(x);
    float e  = __expf(-2.0f * ax);
    float r  = __fdividef(1.0f - e, 1.0f + e);
    return copysignf(r, x);
}

// ============================================================================
// Prep: split all 10 weight matrices into bf16 hi/lo, padded [j][136] rows.
// ============================================================================
__global__ void prep_weights(const float* __restrict__ Wih0,
                             const float* __restrict__ Whh0,
                             const float* __restrict__ WihS,
                             const float* __restrict__ WhhS){
    int slot = blockIdx.x;
    for (int idx = threadIdx.x; idx < 17408; idx += blockDim.x){
        int j = idx / 136, k = idx % 136;
        float w = 0.0f;
        if (slot == 0)      { if (k < 5)   w = Wih0[j*5 + k]; }
        else if (slot == 1) { if (k < 128) w = Whh0[j*128 + k]; }
        else if (slot & 1)  { if (k < 128) w = WhhS[((slot>>1)-1)*16384 + j*128 + k]; }
        else                { if (k < 128) w = WihS[((slot>>1)-1)*16384 + j*128 + k]; }
        __nv_bfloat16 hi = __float2bfloat16(w);
        __nv_bfloat16 lo = __float2bfloat16(w - __bfloat162float(hi));
        g_Whi[slot][idx] = hi;
        g_Wlo[slot][idx] = lo;
    }
}

// async copy one matrix (hi+lo halves) into the SMEM W region
__device__ __forceinline__ void copyW_async(int slot, uint32_t sbW, int tid){
    const char* gh = (const char*)g_Whi[slot];
    const char* gl = (const char*)g_Wlo[slot];
    #pragma unroll 5
    for (int i = tid; i < 2176; i += NT){
        cp_async16(sbW + i*16,                 gh + i*16);
        cp_async16(sbW + W_HALF_BYTES + i*16,  gl + i*16);
    }
    CP_ASYNC_COMMIT();
}

// ============================================================================
__global__ void __launch_bounds__(NT)
rnn_mma(const float* __restrict__ x,
        const float* __restrict__ bih0, const float* __restrict__ bhh0,
        const float* __restrict__ bihS, const float* __restrict__ bhhS,
        const float* __restrict__ Wfc,  const float* __restrict__ bfc,
        float* __restrict__ out, int Btot)
{
    extern __shared__ __align__(16) char smem[];
    const uint32_t sb = smem_u32(smem);
    const int tid  = threadIdx.x;
    const int wid  = tid >> 5, lane = tid & 31;
    const int g    = lane >> 2, c = lane & 3;
    const int grp  = wid >> 2;               // batch group 0..3 (spans all SMSPs)
    const int m0   = grp * 16;               // group's 16 batch rows
    const int n0   = (wid & 3) * 32;         // warp's hidden-col base
    const long long baseb = (long long)blockIdx.x * MB;

    float* b2  = (float*)(smem + OFF_B2);
    float* wfc = (float*)(smem + OFF_WFC);

    // ---- per-lane ldmatrix byte offsets (within a tile) ----
    // A (m16k16): tiles {r0-7,k0},{r8-15,k0},{r0-7,k8},{r8-15,k8}
    const int aRow = m0 + (lane & 7) + ((lane >> 3) & 1) * 8;
    const int aK8  = (lane >> 4) * 8;
    const uint32_t aOff = (uint32_t)(aRow * ROWB + aK8 * 2);
    // B pair (2 nf per x4): tiles {j0-7,k0},{j0-7,k8},{j8-15,k0},{j8-15,k8}
    const int bRow = (lane & 7) + (lane >> 4) * 8;
    const int bK8  = ((lane >> 3) & 1) * 8;
    const uint32_t bOff0 = (uint32_t)((n0 + bRow) * ROWB + bK8 * 2);        // nf0,nf1
    const uint32_t bOff1 = (uint32_t)((n0 + 16 + bRow) * ROWB + bK8 * 2);   // nf2,nf3

    // ---- stage wfc + x tiles (bf16 hi/lo split, [64][8 words]) ----
    if (tid < 128) wfc[tid] = Wfc[tid];
    if (tid < 256){
        int b = tid >> 2, t = tid & 3;
        long long gb = baseb + b;
        float xv[5];
        #pragma unroll
        for (int f = 0; f < 5; f++)
            xv[f] = (gb < Btot) ? x[gb*20 + f*4 + t] : 0.0f;
        uint32_t* xh = (uint32_t*)(smem + OFF_X + t*X_PAIR);
        uint32_t* xl = xh + 512;
        #pragma unroll
        for (int w = 0; w < 8; w++){
            float v0 = (2*w   < 5) ? xv[2*w]   : 0.0f;
            float v1 = (2*w+1 < 5) ? xv[2*w+1] : 0.0f;
            __nv_bfloat16 h0 = __float2bfloat16(v0);
            __nv_bfloat16 h1 = __float2bfloat16(v1);
            __nv_bfloat16 l0 = __float2bfloat16(v0 - __bfloat162float(h0));
            __nv_bfloat16 l1 = __float2bfloat16(v1 - __bfloat162float(h1));
            xh[b*8 + w] = (uint32_t)(*(unsigned short*)&h0) | ((uint32_t)(*(unsigned short*)&h1) << 16);
            xl[b*8 + w] = (uint32_t)(*(unsigned short*)&l0) | ((uint32_t)(*(unsigned short*)&l1) << 16);
        }
    }

    float acc[64];                           // [t][nf][4]
    const uint32_t whAddr = sb + OFF_W;
    const uint32_t wlAddr = sb + OFF_W + W_HALF_BYTES;
    const uint32_t* whW = (const uint32_t*)(smem + OFF_W);
    const uint32_t* wlW = whW + (W_HALF_BYTES >> 2);

    #pragma unroll 1
    for (int l = 0; l < NLAYER; l++){
        __syncthreads();                     // all reads of previous W done
        copyW_async(2*l, sb + OFF_W, tid);
        if (tid < 128)
            b2[tid] = (l == 0) ? bih0[tid] + bhh0[tid]
                               : bihS[(l-1)*128 + tid] + bhhS[(l-1)*128 + tid];
        CP_ASYNC_WAIT();
        __syncthreads();

        // ---- init acc with bias ----
        #pragma unroll
        for (int nf = 0; nf < 4; nf++){
            float bv0 = b2[n0 + nf*8 + c*2];
            float bv1 = b2[n0 + nf*8 + c*2 + 1];
            #pragma unroll
            for (int t = 0; t < 4; t++){
                float* cc = &acc[(t*4 + nf)*4];
                cc[0] = bv0; cc[1] = bv1; cc[2] = bv0; cc[3] = bv1;
            }
        }

        // ---- pass A: acc[t] += Wih . h_prev[t] (no barriers needed) ----
        if (l == 0){
            // one K=16 step from x tiles (scalar LDS; tiny)
            uint32_t bh[8], bl[8];
            #pragma unroll
            for (int nf = 0; nf < 4; nf++){
                int jw = (n0 + nf*8 + g)*HPW + c;
                bh[nf*2]   = whW[jw]; bh[nf*2+1] = whW[jw + 4];
                bl[nf*2]   = wlW[jw]; bl[nf*2+1] = wlW[jw + 4];
            }
            #pragma unroll
            for (int t = 0; t < 4; t++){
                const uint32_t* xh = (const uint32_t*)(smem + OFF_X + t*X_PAIR);
                const uint32_t* xl = xh + 512;
                int rw = (m0 + g)*8 + c;
                uint32_t ah0 = xh[rw], ah1 = xh[rw + 64];
                uint32_t ah2 = xh[rw + 4], ah3 = xh[rw + 68];
                uint32_t al0 = xl[rw], al1 = xl[rw + 64];
                uint32_t al2 = xl[rw + 4], al3 = xl[rw + 68];
                float* ct = &acc[t*16];
                #pragma unroll
                for (int nf = 0; nf < 4; nf++)
                    mma16816(ct + nf*4, ah0,ah1,ah2,ah3, bh[nf*2], bh[nf*2+1]);
                #pragma unroll
                for (int nf = 0; nf < 4; nf++)
                    mma16816(ct + nf*4, ah0,ah1,ah2,ah3, bl[nf*2], bl[nf*2+1]);
                #pragma unroll
                for (int nf = 0; nf < 4; nf++)
                    mma16816(ct + nf*4, al0,al1,al2,al3, bh[nf*2], bh[nf*2+1]);
            }
        } else {
            #pragma unroll 1
            for (int kk = 0; kk < 8; kk++){
                uint32_t kb = kk * 32;       // 16 bf16 = 32 bytes per k-chunk
                uint32_t bh[8], bl[8];
                ldm4(bh,     whAddr + bOff0 + kb);
                ldm4(bh + 4, whAddr + bOff1 + kb);
                ldm4(bl,     wlAddr + bOff0 + kb);
                ldm4(bl + 4, wlAddr + bOff1 + kb);
                #pragma unroll
                for (int t = 0; t < 4; t++){
                    uint32_t hAddr = sb + OFF_H + t*H_PAIR + aOff + kb;
                    uint32_t ah[4], al[4];
                    ldm4(ah, hAddr);
                    ldm4(al, hAddr + H_TILE_BYTES);
                    float* ct = &acc[t*16];
                    #pragma unroll
                    for (int nf = 0; nf < 4; nf++)
                        mma16816(ct + nf*4, ah[0],ah[1],ah[2],ah[3], bh[nf*2], bh[nf*2+1]);
                    #pragma unroll
                    for (int nf = 0; nf < 4; nf++)
                        mma16816(ct + nf*4, ah[0],ah[1],ah[2],ah[3], bl[nf*2], bl[nf*2+1]);
                    #pragma unroll
                    for (int nf = 0; nf < 4; nf++)
                        mma16816(ct + nf*4, al[0],al[1],al[2],al[3], bh[nf*2], bh[nf*2+1]);
                }
            }
        }

        // ---- swap W region to W_hh(l) ----
        __syncthreads();                     // pass-A reads of Wih done
        copyW_async(2*l + 1, sb + OFF_W, tid);
        CP_ASYNC_WAIT();
        __syncthreads();

        // ---- pass B: sequential timesteps; 128-thread group barriers ----
        #pragma unroll
        for (int t = 0; t < 4; t++){
            if (t > 0){
                float* ct = &acc[t*16];
                #pragma unroll 1
                for (int kk = 0; kk < 8; kk++){
                    uint32_t kb = kk * 32;
                    uint32_t bh[8], bl[8];
                    ldm4(bh,     whAddr + bOff0 + kb);
                    ldm4(bh + 4, whAddr + bOff1 + kb);
                    ldm4(bl,     wlAddr + bOff0 + kb);
                    ldm4(bl + 4, wlAddr + bOff1 + kb);
                    uint32_t hAddr = sb + OFF_H + (t-1)*H_PAIR + aOff + kb;
                    uint32_t ah[4], al[4];
                    ldm4(ah, hAddr);
                    ldm4(al, hAddr + H_TILE_BYTES);
                    #pragma unroll
                    for (int nf = 0; nf < 4; nf++)
                        mma16816(ct + nf*4, ah[0],ah[1],ah[2],ah[3], bh[nf*2], bh[nf*2+1]);
                    #pragma unroll
                    for (int nf = 0; nf < 4; nf++)
                        mma16816(ct + nf*4, ah[0],ah[1],ah[2],ah[3], bl[nf*2], bl[nf*2+1]);
                    #pragma unroll
                    for (int nf = 0; nf < 4; nf++)
                        mma16816(ct + nf*4, al[0],al[1],al[2],al[3], bh[nf*2], bh[nf*2+1]);
                }
            }
            // epilogue: h_t = tanh(acc[t]); split; store (in-place)
            uint32_t* hh = (uint32_t*)(smem + OFF_H + t*H_PAIR);
            uint32_t* hl = hh + (H_TILE_BYTES >> 2);
            #pragma unroll
            for (int nf = 0; nf < 4; nf++){
                float* cc = &acc[(t*4 + nf)*4];
                #pragma unroll
                for (int p = 0; p < 2; p++){
                    int row = m0 + g + p*8;
                    float h0 = fast_tanh(cc[2*p]);
                    float h1 = fast_tanh(cc[2*p + 1]);
                    __nv_bfloat16 hb0 = __float2bfloat16(h0);
                    __nv_bfloat16 hb1 = __float2bfloat16(h1);
                    __nv_bfloat16 lb0 = __float2bfloat16(h0 - __bfloat162float(hb0));
                    __nv_bfloat16 lb1 = __float2bfloat16(h1 - __bfloat162float(hb1));
                    int widx = row*HPW + ((n0 + nf*8) >> 1) + c;
                    hh[widx] = (uint32_t)(*(unsigned short*)&hb0)
                             | ((uint32_t)(*(unsigned short*)&hb1) << 16);
                    hl[widx] = (uint32_t)(*(unsigned short*)&lb0)
                             | ((uint32_t)(*(unsigned short*)&lb1) << 16);
                }
            }
            if (t < 3) GROUP_BAR(grp);       // h[t] visible within this batch group
            // t==3: next-layer __syncthreads (or the head's) provides ordering
        }
    }

    __syncthreads();                         // all groups' h[3] complete

    // ---- head: out[b] = dot(h3[b], wfc) + bfc ----
    if (tid < 256){
        int b = tid >> 2, q = tid & 3;
        const uint32_t* hh = (const uint32_t*)(smem + OFF_H + 3*H_PAIR);
        const uint32_t* hl = hh + (H_TILE_BYTES >> 2);
        float s = 0.0f;
        #pragma unroll
        for (int w = 0; w < 16; w++){
            int widx = b*HPW + q*16 + w;
            uint32_t uh = hh[widx], ul = hl[widx];
            __nv_bfloat162 vh = *(__nv_bfloat162*)&uh;
            __nv_bfloat162 vl = *(__nv_bfloat162*)&ul;
            int j = q*32 + 2*w;
            s = fmaf(__bfloat162float(vh.x) + __bfloat162float(vl.x), wfc[j],   s);
            s = fmaf(__bfloat162float(vh.y) + __bfloat162float(vl.y), wfc[j+1], s);
        }
        ((float*)(smem + OFF_SPART))[tid] = s;
    }
    __syncthreads();
    if (tid < 64){
        const float* sp = (const float*)(smem + OFF_SPART);
        long long gb = baseb + tid;
        if (gb < Btot)
            out[gb] = sp[tid*4] + sp[tid*4+1] + sp[tid*4+2] + sp[tid*4+3] + bfc[0];
    }
}

// ============================================================================
extern "C" void kernel_launch(void* const* d_in, const int* in_sizes, int n_in,
                              void* d_out, int out_size)
{
    const float* x    = (const float*)d_in[0];
    const float* Wih0 = (const float*)d_in[1];
    const float* Whh0 = (const float*)d_in[2];
    const float* bih0 = (const float*)d_in[3];
    const float* bhh0 = (const float*)d_in[4];
    const float* WihS = (const float*)d_in[5];
    const float* WhhS = (const float*)d_in[6];
    const float* bihS = (const float*)d_in[7];
    const float* bhhS = (const float*)d_in[8];
    const float* Wfc  = (const float*)d_in[9];
    const float* bfc  = (const float*)d_in[10];
    float* out = (float*)d_out;

    int Btot = in_sizes[0] / 20;
    int grid = (Btot + MB - 1) / MB;

    cudaFuncSetAttribute(rnn_mma,
                         cudaFuncAttributeMaxDynamicSharedMemorySize, SMEM_BYTES);

    prep_weights<<<10, 256>>>(Wih0, Whh0, WihS, WhhS);
    rnn_mma<<<grid, NT, SMEM_BYTES>>>(x, bih0, bhh0, bihS, bhhS,
                                      Wfc, bfc, out, Btot);
}